// round 7
// baseline (speedup 1.0000x reference)
#include <cuda_runtime.h>
#include <cuda_bf16.h>
#include <cstdint>

constexpr int NN   = 50000;
constexpr int EMAX = 640000;

__device__ int   g_cnt[NN];
__device__ int   g_fill[NN];
__device__ int   g_rowptr[NN + 1];
__device__ int   g_col[EMAX];

// bf16 hi/lo planes — alignas(16): we access these with uint4/uint2 vectors,
// and bf16 arrays are otherwise only 2-byte aligned (misalign = device trap).
__device__ alignas(16) __nv_bfloat16 g_ah[(size_t)NN * 256];   // [mean(x) | x] hi
__device__ alignas(16) __nv_bfloat16 g_al[(size_t)NN * 256];   // [mean(x) | x] lo
__device__ alignas(16) __nv_bfloat16 g_hh[(size_t)NN * 256];   // h hi
__device__ alignas(16) __nv_bfloat16 g_hl[(size_t)NN * 256];   // h lo
__device__ alignas(16) __nv_bfloat16 g_w1h[256 * 256];         // [W1_l | W1_r] hi
__device__ alignas(16) __nv_bfloat16 g_w1l[256 * 256];
__device__ alignas(16) __nv_bfloat16 g_w2h[256 * 256];         // [W2_l ; W2_r] hi
__device__ alignas(16) __nv_bfloat16 g_w2l[256 * 256];
__device__ float g_c2[(size_t)NN * 256];                       // [y | part] f32

// ---------------------------------------------------------------------------
// split helpers
// ---------------------------------------------------------------------------
__device__ __forceinline__ void split2(float x, float y,
                                       uint32_t& hi, uint32_t& lo) {
    __nv_bfloat162 h = __floats2bfloat162_rn(x, y);
    __nv_bfloat162 l = __floats2bfloat162_rn(x - __bfloat162float(h.x),
                                             y - __bfloat162float(h.y));
    hi = *reinterpret_cast<uint32_t*>(&h);
    lo = *reinterpret_cast<uint32_t*>(&l);
}

__device__ __forceinline__ void split4_store(float4 v,
                                             __nv_bfloat16* hp,
                                             __nv_bfloat16* lp) {
    uint32_t h01, l01, h23, l23;
    split2(v.x, v.y, h01, l01);
    split2(v.z, v.w, h23, l23);
    uint2 hv = make_uint2(h01, h23);
    uint2 lv = make_uint2(l01, l23);
    *reinterpret_cast<uint2*>(hp) = hv;
    *reinterpret_cast<uint2*>(lp) = lv;
}

// ---------------------------------------------------------------------------
// CSR build
// ---------------------------------------------------------------------------
__global__ void zero_int2() {
    int i = blockIdx.x * blockDim.x + threadIdx.x;
    if (i < NN) { g_cnt[i] = 0; g_fill[i] = 0; }
}

__global__ void hist_kernel(const int* __restrict__ dst, int E) {
    int i = blockIdx.x * blockDim.x + threadIdx.x;
    int stride = gridDim.x * blockDim.x;
    for (; i < E; i += stride)
        atomicAdd(&g_cnt[dst[i]], 1);
}

__global__ void __launch_bounds__(1024, 1) scan_kernel() {
    __shared__ int sums[1024];
    const int tid = threadIdx.x;
    const int CH = (NN + 1023) / 1024;
    const int base = tid * CH;

    int local = 0;
    for (int i = 0; i < CH; i++) {
        int idx = base + i;
        if (idx < NN) local += g_cnt[idx];
    }
    sums[tid] = local;
    __syncthreads();
    for (int d = 1; d < 1024; d <<= 1) {
        int v = (tid >= d) ? sums[tid - d] : 0;
        __syncthreads();
        sums[tid] += v;
        __syncthreads();
    }
    int off = sums[tid] - local;
    for (int i = 0; i < CH; i++) {
        int idx = base + i;
        if (idx < NN) {
            g_rowptr[idx] = off;
            off += g_cnt[idx];
        }
    }
    if (tid == 1023) g_rowptr[NN] = off;
}

__global__ void place_kernel(const int* __restrict__ src,
                             const int* __restrict__ dst, int E) {
    int i = blockIdx.x * blockDim.x + threadIdx.x;
    int stride = gridDim.x * blockDim.x;
    for (; i < E; i += stride) {
        int d = dst[i];
        int pos = atomicAdd(&g_fill[d], 1);
        g_col[g_rowptr[d] + pos] = src[i];
    }
}

// ---------------------------------------------------------------------------
// One-shot converters
// ---------------------------------------------------------------------------
// x f32 [NN][128] -> cols 128..255 of g_ah/g_al
__global__ void convert_x(const float* __restrict__ x) {
    int i = blockIdx.x * blockDim.x + threadIdx.x;
    if (i >= NN * 32) return;
    int m = i >> 5, f = i & 31;
    float4 v = __ldg(reinterpret_cast<const float4*>(x) + i);
    size_t off = (size_t)m * 256 + 128 + f * 4;
    split4_store(v, g_ah + off, g_al + off);
}

// weights -> cat planes. 32768 float4 tasks: first half w1cat, second w2cat.
__global__ void convert_w(const float* __restrict__ W1_l,
                          const float* __restrict__ W1_r,
                          const float* __restrict__ W2_l,
                          const float* __restrict__ W2_r) {
    int idx = blockIdx.x * blockDim.x + threadIdx.x;
    if (idx >= 2 * 256 * 64) return;
    if (idx < 256 * 64) {
        int n = idx >> 6, f = idx & 63, k = f * 4;
        const float* src = (k < 128) ? (W1_l + (size_t)n * 128 + k)
                                     : (W1_r + (size_t)n * 128 + (k - 128));
        float4 v = *reinterpret_cast<const float4*>(src);
        size_t off = (size_t)n * 256 + k;
        split4_store(v, g_w1h + off, g_w1l + off);
    } else {
        int t = idx - 256 * 64;
        int n = t >> 6, f = t & 63, k = f * 4;
        const float* src = (n < 128) ? (W2_l + (size_t)n * 256 + k)
                                     : (W2_r + (size_t)(n - 128) * 256 + k);
        float4 v = *reinterpret_cast<const float4*>(src);
        size_t off = (size_t)n * 256 + k;
        split4_store(v, g_w2h + off, g_w2l + off);
    }
}

// ---------------------------------------------------------------------------
// Gather-mean: one warp per node, 1 float4 per lane.
// FIN=0: mean(x rows) -> bf16 hi/lo planes, cols 0..127 of g_ah/g_al
// FIN=1: out = mean(c2[:,0:128] rows) + c2[node,128..255] + b2  (f32 out)
// ---------------------------------------------------------------------------
template <int FIN>
__global__ void __launch_bounds__(256)
gather_mean(const float* __restrict__ feat, int fstride,
            const float* __restrict__ c2,
            const float* __restrict__ b2,
            float* __restrict__ out) {
    int node = (blockIdx.x * blockDim.x + threadIdx.x) >> 5;
    if (node >= NN) return;
    int lane = threadIdx.x & 31;
    int beg = __ldg(&g_rowptr[node]);
    int end = __ldg(&g_rowptr[node + 1]);

    float4 a0 = make_float4(0.f, 0.f, 0.f, 0.f);
    float4 a1 = make_float4(0.f, 0.f, 0.f, 0.f);
    int e = beg;
    for (; e + 1 < end; e += 2) {
        int s0 = __ldg(&g_col[e]);
        int s1 = __ldg(&g_col[e + 1]);
        float4 v0 = __ldg(reinterpret_cast<const float4*>(feat + (size_t)s0 * fstride) + lane);
        float4 v1 = __ldg(reinterpret_cast<const float4*>(feat + (size_t)s1 * fstride) + lane);
        a0.x += v0.x; a0.y += v0.y; a0.z += v0.z; a0.w += v0.w;
        a1.x += v1.x; a1.y += v1.y; a1.z += v1.z; a1.w += v1.w;
    }
    if (e < end) {
        int s0 = __ldg(&g_col[e]);
        float4 v0 = __ldg(reinterpret_cast<const float4*>(feat + (size_t)s0 * fstride) + lane);
        a0.x += v0.x; a0.y += v0.y; a0.z += v0.z; a0.w += v0.w;
    }
    float inv = 1.0f / (float)max(end - beg, 1);
    float4 r;
    r.x = (a0.x + a1.x) * inv;
    r.y = (a0.y + a1.y) * inv;
    r.z = (a0.z + a1.z) * inv;
    r.w = (a0.w + a1.w) * inv;

    if (FIN) {
        float4 p = *reinterpret_cast<const float4*>(c2 + (size_t)node * 256 + 128 + lane * 4);
        float4 b = __ldg(reinterpret_cast<const float4*>(b2) + lane);
        r.x += p.x + b.x;
        r.y += p.y + b.y;
        r.z += p.z + b.z;
        r.w += p.w + b.w;
        *(reinterpret_cast<float4*>(out + (size_t)node * 128) + lane) = r;
    } else {
        size_t off = (size_t)node * 256 + lane * 4;
        split4_store(r, g_ah + off, g_al + off);
    }
}

// ---------------------------------------------------------------------------
// mma.sync m16n8k16 bf16 (baseline PTX)
// ---------------------------------------------------------------------------
__device__ __forceinline__ void mma_bf16(float* d, const uint32_t* a,
                                         const uint32_t* b) {
    asm volatile(
        "mma.sync.aligned.m16n8k16.row.col.f32.bf16.bf16.f32 "
        "{%0,%1,%2,%3}, {%4,%5,%6,%7}, {%8,%9}, {%0,%1,%2,%3};"
        : "+f"(d[0]), "+f"(d[1]), "+f"(d[2]), "+f"(d[3])
        : "r"(a[0]), "r"(a[1]), "r"(a[2]), "r"(a[3]), "r"(b[0]), "r"(b[1]));
}

// ---------------------------------------------------------------------------
// Split-bf16 HMMA GEMM over pre-split planes.
// C[M,256] = act(A[M,256] @ B[256,256]^T (+bias))
// 3-term: hi*hi + hi*lo + lo*hi, fp32 accum.
// MODE 1: epilogue relu+bias, writes h hi/lo planes.
// MODE 2: epilogue plain, writes f32 C.
// ---------------------------------------------------------------------------
constexpr int PAD = 40;

template <int MODE>
__global__ void __launch_bounds__(256, 2)
sage_gemm(const __nv_bfloat16* __restrict__ Ah, const __nv_bfloat16* __restrict__ Al,
          const __nv_bfloat16* __restrict__ Bh, const __nv_bfloat16* __restrict__ Bl,
          const float* __restrict__ bias,
          float* __restrict__ Cf,
          __nv_bfloat16* __restrict__ Chh, __nv_bfloat16* __restrict__ Chl,
          int M) {
    __shared__ alignas(16) __nv_bfloat16 As_hi[128 * PAD];
    __shared__ alignas(16) __nv_bfloat16 As_lo[128 * PAD];
    __shared__ alignas(16) __nv_bfloat16 Bs_hi[128 * PAD];
    __shared__ alignas(16) __nv_bfloat16 Bs_lo[128 * PAD];

    const int tid = threadIdx.x;
    const int wid = tid >> 5, lane = tid & 31;
    const int wm = wid & 3, wn = wid >> 2;
    const int m0 = blockIdx.x * 128, n0 = blockIdx.y * 128;

    float acc[2][8][4];
#pragma unroll
    for (int i = 0; i < 2; i++)
#pragma unroll
        for (int j = 0; j < 8; j++)
#pragma unroll
            for (int q = 0; q < 4; q++) acc[i][j][q] = 0.f;

    const uint4 z4 = make_uint4(0, 0, 0, 0);

    for (int ch = 0; ch < 8; ch++) {
        const int ka = ch * 32;
        // ---- A tile: 128 rows x 32 bf16 per plane, pure uint4 copies ----
#pragma unroll
        for (int it = 0; it < 2; it++) {
            int idx = it * 256 + tid;
            int row = idx >> 2, f = idx & 3;
            int gm = m0 + row;
            uint4 vh = z4, vl = z4;
            if (gm < M) {
                const size_t go = (size_t)gm * 256 + ka + f * 8;
                vh = *reinterpret_cast<const uint4*>(Ah + go);
                vl = *reinterpret_cast<const uint4*>(Al + go);
            }
            int off = row * PAD + f * 8;
            *reinterpret_cast<uint4*>(&As_hi[off]) = vh;
            *reinterpret_cast<uint4*>(&As_lo[off]) = vl;
        }
        // ---- B tile: 128 n-rows x 32 bf16 per plane ----
#pragma unroll
        for (int it = 0; it < 2; it++) {
            int idx = it * 256 + tid;
            int row = idx >> 2, f = idx & 3;
            const size_t go = (size_t)(n0 + row) * 256 + ka + f * 8;
            uint4 vh = *reinterpret_cast<const uint4*>(Bh + go);
            uint4 vl = *reinterpret_cast<const uint4*>(Bl + go);
            int off = row * PAD + f * 8;
            *reinterpret_cast<uint4*>(&Bs_hi[off]) = vh;
            *reinterpret_cast<uint4*>(&Bs_lo[off]) = vl;
        }
        __syncthreads();

        const int r = lane >> 2, c = (lane & 3) * 2;
#pragma unroll
        for (int ks = 0; ks < 2; ks++) {
            const int k = ks * 16;
            uint32_t ahi[2][4], alo[2][4];
#pragma unroll
            for (int mt = 0; mt < 2; mt++) {
                int rr = wm * 32 + mt * 16 + r;
                ahi[mt][0] = *reinterpret_cast<const uint32_t*>(&As_hi[rr * PAD + k + c]);
                ahi[mt][1] = *reinterpret_cast<const uint32_t*>(&As_hi[(rr + 8) * PAD + k + c]);
                ahi[mt][2] = *reinterpret_cast<const uint32_t*>(&As_hi[rr * PAD + k + c + 8]);
                ahi[mt][3] = *reinterpret_cast<const uint32_t*>(&As_hi[(rr + 8) * PAD + k + c + 8]);
                alo[mt][0] = *reinterpret_cast<const uint32_t*>(&As_lo[rr * PAD + k + c]);
                alo[mt][1] = *reinterpret_cast<const uint32_t*>(&As_lo[(rr + 8) * PAD + k + c]);
                alo[mt][2] = *reinterpret_cast<const uint32_t*>(&As_lo[rr * PAD + k + c + 8]);
                alo[mt][3] = *reinterpret_cast<const uint32_t*>(&As_lo[(rr + 8) * PAD + k + c + 8]);
            }
#pragma unroll
            for (int nt = 0; nt < 8; nt++) {
                int nn = wn * 64 + nt * 8 + (lane >> 2);
                int kb = k + (lane & 3) * 2;
                uint32_t bhi[2], blo[2];
                bhi[0] = *reinterpret_cast<const uint32_t*>(&Bs_hi[nn * PAD + kb]);
                bhi[1] = *reinterpret_cast<const uint32_t*>(&Bs_hi[nn * PAD + kb + 8]);
                blo[0] = *reinterpret_cast<const uint32_t*>(&Bs_lo[nn * PAD + kb]);
                blo[1] = *reinterpret_cast<const uint32_t*>(&Bs_lo[nn * PAD + kb + 8]);
#pragma unroll
                for (int mt = 0; mt < 2; mt++) {
                    mma_bf16(acc[mt][nt], ahi[mt], bhi);
                    mma_bf16(acc[mt][nt], ahi[mt], blo);
                    mma_bf16(acc[mt][nt], alo[mt], bhi);
                }
            }
        }
        __syncthreads();
    }

    // ---- epilogue ----
#pragma unroll
    for (int mt = 0; mt < 2; mt++) {
#pragma unroll
        for (int nt = 0; nt < 8; nt++) {
            int m = m0 + wm * 32 + mt * 16 + (lane >> 2);
            int n = n0 + wn * 64 + nt * 8 + (lane & 3) * 2;
            if (MODE == 1) {
                float2 bz = *reinterpret_cast<const float2*>(bias + n);
                if (m < M) {
                    float vx = fmaxf(acc[mt][nt][0] + bz.x, 0.f);
                    float vy = fmaxf(acc[mt][nt][1] + bz.y, 0.f);
                    uint32_t hi, lo;
                    split2(vx, vy, hi, lo);
                    *reinterpret_cast<uint32_t*>(Chh + (size_t)m * 256 + n) = hi;
                    *reinterpret_cast<uint32_t*>(Chl + (size_t)m * 256 + n) = lo;
                }
                if (m + 8 < M) {
                    float vx = fmaxf(acc[mt][nt][2] + bz.x, 0.f);
                    float vy = fmaxf(acc[mt][nt][3] + bz.y, 0.f);
                    uint32_t hi, lo;
                    split2(vx, vy, hi, lo);
                    *reinterpret_cast<uint32_t*>(Chh + (size_t)(m + 8) * 256 + n) = hi;
                    *reinterpret_cast<uint32_t*>(Chl + (size_t)(m + 8) * 256 + n) = lo;
                }
            } else {
                if (m < M) {
                    float2 v = make_float2(acc[mt][nt][0], acc[mt][nt][1]);
                    *reinterpret_cast<float2*>(Cf + (size_t)m * 256 + n) = v;
                }
                if (m + 8 < M) {
                    float2 v = make_float2(acc[mt][nt][2], acc[mt][nt][3]);
                    *reinterpret_cast<float2*>(Cf + (size_t)(m + 8) * 256 + n) = v;
                }
            }
        }
    }
}

// ---------------------------------------------------------------------------
// Launch
// ---------------------------------------------------------------------------
extern "C" void kernel_launch(void* const* d_in, const int* in_sizes, int n_in,
                              void* d_out, int out_size) {
    const float* x    = (const float*)d_in[0];
    const int*   ei   = (const int*)d_in[1];
    const float* W1_l = (const float*)d_in[2];
    const float* b1_l = (const float*)d_in[3];
    const float* W1_r = (const float*)d_in[4];
    const float* W2_l = (const float*)d_in[5];
    const float* b2_l = (const float*)d_in[6];
    const float* W2_r = (const float*)d_in[7];
    float* out = (float*)d_out;

    const int E = in_sizes[1] / 2;
    const int* esrc = ei;
    const int* edst = ei + E;

    void *p_ah, *p_al, *p_hh, *p_hl, *p_w1h, *p_w1l, *p_w2h, *p_w2l, *p_c2;
    cudaGetSymbolAddress(&p_ah,  g_ah);
    cudaGetSymbolAddress(&p_al,  g_al);
    cudaGetSymbolAddress(&p_hh,  g_hh);
    cudaGetSymbolAddress(&p_hl,  g_hl);
    cudaGetSymbolAddress(&p_w1h, g_w1h);
    cudaGetSymbolAddress(&p_w1l, g_w1l);
    cudaGetSymbolAddress(&p_w2h, g_w2h);
    cudaGetSymbolAddress(&p_w2l, g_w2l);
    cudaGetSymbolAddress(&p_c2,  g_c2);
    float* c2 = (float*)p_c2;

    // ---- CSR build (by dst) ----
    zero_int2<<<(NN + 255) / 256, 256>>>();
    hist_kernel<<<(E + 511) / 512, 256>>>(edst, E);
    scan_kernel<<<1, 1024>>>();
    place_kernel<<<(E + 511) / 512, 256>>>(esrc, edst, E);

    // ---- one-shot converts ----
    convert_x<<<(NN * 32 + 255) / 256, 256>>>(x);
    convert_w<<<(2 * 256 * 64 + 255) / 256, 256>>>(W1_l, W1_r, W2_l, W2_r);

    // ---- mean(x) -> A-plane cols 0..127 (bf16 hi/lo) ----
    {
        int blocks = (NN * 32 + 255) / 256;
        gather_mean<0><<<blocks, 256>>>(x, 128, nullptr, nullptr, nullptr);
    }

    const dim3 grid((NN + 127) / 128, 2);

    // ---- h = relu([mean|x] @ W1cat^T + b1) -> h hi/lo planes ----
    sage_gemm<1><<<grid, 256>>>((__nv_bfloat16*)p_ah, (__nv_bfloat16*)p_al,
                                (__nv_bfloat16*)p_w1h, (__nv_bfloat16*)p_w1l,
                                b1_l, nullptr,
                                (__nv_bfloat16*)p_hh, (__nv_bfloat16*)p_hl, NN);

    // ---- [y | part] = h @ W2cat^T -> f32 c2 ----
    sage_gemm<2><<<grid, 256>>>((__nv_bfloat16*)p_hh, (__nv_bfloat16*)p_hl,
                                (__nv_bfloat16*)p_w2h, (__nv_bfloat16*)p_w2l,
                                nullptr, c2, nullptr, nullptr, NN);

    // ---- out = mean(y rows) + part + b2 ----
    {
        int blocks = (NN * 32 + 255) / 256;
        gather_mean<1><<<blocks, 256>>>(c2, 256, c2, b2_l, out);
    }
}